// round 4
// baseline (speedup 1.0000x reference)
#include <cuda_runtime.h>
#include <cstdint>
#include <cstddef>

#define T_STEPS 512
#define BATCH   128
#define DIN     512
#define DH      1024
#define M_TOTAL (T_STEPS * BATCH)   // 65536
#define NKC     8                   // K-chunks in the scan split-K
#define SCAN_CTAS 128
#define SCAN_THREADS 256

// ---------------- scratch (static __device__ — allocation-free) ----------------
__device__ float g_Wx[(size_t)T_STEPS * BATCH * DH];   // 256 MB: encoder output
__device__ float g_hT[DH * BATCH];                     // h transposed: [H][B]
__device__ float g_part[NKC * BATCH * DH];             // split-K partials: 4 MB
__device__ unsigned g_count;                           // barrier arrival counter (zero-init)
__device__ volatile unsigned g_gen;                    // barrier generation (monotonic)

// ---------------- f32x2 packed-FMA helpers (Blackwell FFMA2 path) ----------------
__device__ __forceinline__ unsigned long long pack2(float x) {
    unsigned long long r;
    asm("mov.b64 %0, {%1, %1};" : "=l"(r) : "f"(x));
    return r;
}
__device__ __forceinline__ void ffma2(unsigned long long& d,
                                      unsigned long long a,
                                      unsigned long long b) {
    asm("fma.rn.f32x2 %0, %1, %2, %0;" : "+l"(d) : "l"(a), "l"(b));
}
__device__ __forceinline__ float2 unpack2(unsigned long long v) {
    float2 f;
    asm("mov.b64 {%0, %1}, %2;" : "=f"(f.x), "=f"(f.y) : "l"(v));
    return f;
}

// ---------------- software grid barrier (128 resident CTAs) ----------------
__device__ __forceinline__ void grid_barrier() {
    __syncthreads();
    if (threadIdx.x == 0) {
        unsigned gen = g_gen;          // read generation BEFORE arriving
        __threadfence();               // order data writes + gen read before arrival
        unsigned a = atomicAdd(&g_count, 1u);
        if (a == gridDim.x - 1) {
            g_count = 0;
            __threadfence();           // reset visible before release
            g_gen = gen + 1;           // release
        } else {
            while (g_gen == gen) { }   // volatile spin (L2)
        }
        __threadfence();               // acquire: gpu-scope fence -> L1 invalidate
    }
    __syncthreads();
}

// =====================================================================
// Kernel 1: encoder GEMM  Wx[m][n] = X[m][:] @ W_enc[:, n] + b_enc[n]
// BM=128, BN=64, BK=16, 256 threads, 8x4 outputs/thread via FFMA2 (row-paired)
// =====================================================================
__global__ __launch_bounds__(256)
void encoder_gemm(const float* __restrict__ X,
                  const float* __restrict__ W,
                  const float* __restrict__ bias) {
    __shared__ float As[16 * 128];   // As[k][m]  (transposed tile)
    __shared__ float Bs[16 * 64];    // Bs[k][n]

    const int m0  = blockIdx.y * 128;
    const int n0  = blockIdx.x * 64;
    const int tid = threadIdx.x;
    const int tc  = tid & 15;        // 16 col-groups x 4 cols
    const int tr  = tid >> 4;        // 16 row-groups x 8 rows

    unsigned long long A[4][4];
#pragma unroll
    for (int i = 0; i < 4; i++)
#pragma unroll
        for (int j = 0; j < 4; j++) A[i][j] = 0ull;

    for (int kb = 0; kb < DIN; kb += 16) {
        // Load A tile (128x16) transposed into As[k][m]
        {
            int f = tid;
#pragma unroll
            for (int it = 0; it < 2; ++it, f += 256) {
                int row = f >> 2;
                int kq  = f & 3;
                float4 v = *(const float4*)(X + (size_t)(m0 + row) * DIN + kb + kq * 4);
                As[(kq * 4 + 0) * 128 + row] = v.x;
                As[(kq * 4 + 1) * 128 + row] = v.y;
                As[(kq * 4 + 2) * 128 + row] = v.z;
                As[(kq * 4 + 3) * 128 + row] = v.w;
            }
        }
        // Load B tile (16x64)
        {
            int row = tid >> 4;
            int c4  = tid & 15;
            float4 v = *(const float4*)(W + (size_t)(kb + row) * DH + n0 + c4 * 4);
            *(float4*)(Bs + row * 64 + c4 * 4) = v;
        }
        __syncthreads();

#pragma unroll
        for (int k = 0; k < 16; k++) {
            const ulonglong2* hp = (const ulonglong2*)(As + k * 128 + tr * 8);
            ulonglong2 a01 = hp[0];
            ulonglong2 a23 = hp[1];
            unsigned long long av[4] = { a01.x, a01.y, a23.x, a23.y };
            float4 w = *(const float4*)(Bs + k * 64 + tc * 4);
            unsigned long long wv[4] = { pack2(w.x), pack2(w.y), pack2(w.z), pack2(w.w) };
#pragma unroll
            for (int rp = 0; rp < 4; rp++)
#pragma unroll
                for (int c = 0; c < 4; c++) ffma2(A[rp][c], av[rp], wv[c]);
        }
        __syncthreads();
    }

    // Epilogue: + b_enc, write Wx
    float4 be = *(const float4*)(bias + n0 + tc * 4);
#pragma unroll
    for (int rp = 0; rp < 4; rp++) {
        float2 c0 = unpack2(A[rp][0]);
        float2 c1 = unpack2(A[rp][1]);
        float2 c2 = unpack2(A[rp][2]);
        float2 c3 = unpack2(A[rp][3]);
        int row = tr * 8 + rp * 2;
        float4 lo = { c0.x + be.x, c1.x + be.y, c2.x + be.z, c3.x + be.w };
        float4 hi = { c0.y + be.x, c1.y + be.y, c2.y + be.z, c3.y + be.w };
        *(float4*)(g_Wx + (size_t)(m0 + row)     * DH + n0 + tc * 4) = lo;
        *(float4*)(g_Wx + (size_t)(m0 + row + 1) * DH + n0 + tc * 4) = hi;
    }
}

// =====================================================================
// Kernel 2: persistent scan. 128 CTAs = 16 col-tiles (64 cols) x 8 K-chunks (128 k).
// Per step: phase1 split-K partial GEMM (W_h slice resident in SMEM),
//           barrier, phase2 reduce+bias+Wx+tanh, barrier.
// h kept transposed in g_hT[H][B] for coalesced k-major staging.
// =====================================================================
__global__ __launch_bounds__(SCAN_THREADS)
void scan_kernel(const float* __restrict__ h0,
                 const float* __restrict__ Wh,
                 const float* __restrict__ bh,
                 float* __restrict__ out) {
    extern __shared__ float smem[];
    float* Ws = smem;                 // [128][64]  W_h slice (persists all steps)
    float* hs = smem + 128 * 64;      // [128][128] h slice (k-major, per step)

    const int tid = threadIdx.x;
    const int cta = blockIdx.x;
    const int jt    = cta & 15;   const int jbase = jt * 64;
    const int kc    = cta >> 4;   const int kbase = kc * 128;
    const int tc  = tid & 15;     // 4 cols each
    const int tr  = tid >> 4;     // 8 rows each

    // Preload W_h slice [kbase..kbase+128) x [jbase..jbase+64) into SMEM (once)
    for (int i = tid; i < 128 * 16; i += SCAN_THREADS) {
        int row = i >> 4, c4 = i & 15;
        *(float4*)(Ws + row * 64 + c4 * 4) =
            *(const float4*)(Wh + (size_t)(kbase + row) * DH + jbase + c4 * 4);
    }
    // Initialize g_hT (transposed h0)
    for (int i = tid + cta * SCAN_THREADS; i < DH * BATCH; i += SCAN_CTAS * SCAN_THREADS) {
        int j = i >> 7;
        int b = i & 127;
        g_hT[i] = h0[(size_t)b * DH + j];
    }
    grid_barrier();

    for (int t = 0; t < T_STEPS; ++t) {
        // -------- phase 1: partial C[b][j] over k in [kbase, kbase+128) --------
        // Stage h slice (coalesced: g_hT is k-major)
        {
            const float4* src = (const float4*)(g_hT + kbase * BATCH);
            float4* dst = (float4*)hs;
            for (int i = tid; i < (128 * 128) / 4; i += SCAN_THREADS) dst[i] = src[i];
        }
        __syncthreads();

        unsigned long long A[4][4];
#pragma unroll
        for (int i = 0; i < 4; i++)
#pragma unroll
            for (int j = 0; j < 4; j++) A[i][j] = 0ull;

#pragma unroll 8
        for (int k = 0; k < 128; k++) {
            const ulonglong2* hp = (const ulonglong2*)(hs + k * 128 + tr * 8);
            ulonglong2 a01 = hp[0];
            ulonglong2 a23 = hp[1];
            unsigned long long av[4] = { a01.x, a01.y, a23.x, a23.y };
            float4 w = *(const float4*)(Ws + k * 64 + tc * 4);
            unsigned long long wv[4] = { pack2(w.x), pack2(w.y), pack2(w.z), pack2(w.w) };
#pragma unroll
            for (int rp = 0; rp < 4; rp++)
#pragma unroll
                for (int c = 0; c < 4; c++) ffma2(A[rp][c], av[rp], wv[c]);
        }

        // Store partials: g_part[kc][b][j]
#pragma unroll
        for (int rp = 0; rp < 4; rp++) {
            float2 c0 = unpack2(A[rp][0]);
            float2 c1 = unpack2(A[rp][1]);
            float2 c2 = unpack2(A[rp][2]);
            float2 c3 = unpack2(A[rp][3]);
            int b = tr * 8 + rp * 2;
            float4 lo = { c0.x, c1.x, c2.x, c3.x };
            float4 hi = { c0.y, c1.y, c2.y, c3.y };
            *(float4*)(g_part + ((size_t)kc * BATCH + b)     * DH + jbase + tc * 4) = lo;
            *(float4*)(g_part + ((size_t)kc * BATCH + b + 1) * DH + jbase + tc * 4) = hi;
        }
        grid_barrier();

        // -------- phase 2: reduce partials + Wx[t] + b_h, tanh, write h --------
        {
            int e4 = cta * SCAN_THREADS + tid;   // float4 index 0..32767
            int e  = e4 * 4;
            int b  = e >> 10;
            int j  = e & 1023;
            float4 s  = *(const float4*)(g_Wx + (size_t)t * BATCH * DH + e);
            float4 bb = *(const float4*)(bh + j);
            s.x += bb.x; s.y += bb.y; s.z += bb.z; s.w += bb.w;
#pragma unroll
            for (int kk = 0; kk < NKC; kk++) {
                float4 p = *(const float4*)(g_part + (size_t)kk * BATCH * DH + e);
                s.x += p.x; s.y += p.y; s.z += p.z; s.w += p.w;
            }
            s.x = tanhf(s.x); s.y = tanhf(s.y); s.z = tanhf(s.z); s.w = tanhf(s.w);
            // write transposed h for next step's coalesced stage
            g_hT[(j + 0) * BATCH + b] = s.x;
            g_hT[(j + 1) * BATCH + b] = s.y;
            g_hT[(j + 2) * BATCH + b] = s.z;
            g_hT[(j + 3) * BATCH + b] = s.w;
            if (t == T_STEPS - 1) *(float4*)(out + e) = s;   // final h in [B][H]
        }
        grid_barrier();
    }
}

// =====================================================================
// Launch
// =====================================================================
extern "C" void kernel_launch(void* const* d_in, const int* in_sizes, int n_in,
                              void* d_out, int out_size) {
    (void)in_sizes; (void)n_in; (void)out_size;
    const float* X     = (const float*)d_in[0];
    const float* h0    = (const float*)d_in[1];
    const float* W_enc = (const float*)d_in[2];
    const float* b_enc = (const float*)d_in[3];
    const float* W_h   = (const float*)d_in[4];
    const float* b_h   = (const float*)d_in[5];
    float* out = (float*)d_out;

    // Encoder: Wx = X @ W_enc + b_enc   (grid 16 x 512)
    dim3 egrid(DH / 64, M_TOTAL / 128);
    encoder_gemm<<<egrid, 256>>>(X, W_enc, b_enc);

    // Persistent scan (single wave: 128 CTAs, 96KB dynamic smem)
    const int scan_smem = (128 * 64 + 128 * 128) * (int)sizeof(float);  // 98304
    cudaFuncSetAttribute(scan_kernel, cudaFuncAttributeMaxDynamicSharedMemorySize, scan_smem);
    scan_kernel<<<SCAN_CTAS, SCAN_THREADS, scan_smem>>>(h0, W_h, b_h, out);
}

// round 5
// speedup vs baseline: 1.1066x; 1.1066x over previous
#include <cuda_runtime.h>
#include <cstdint>
#include <cstddef>

#define T_STEPS 512
#define BATCH   128
#define DIN     512
#define DH      1024
#define M_TOTAL (T_STEPS * BATCH)   // 65536
#define NKC     8                   // K-chunks in the scan split-K
#define SCAN_CTAS 128
#define SCAN_THREADS 512

// ---------------- scratch (static __device__ — allocation-free) ----------------
__device__ float g_Wx[(size_t)T_STEPS * BATCH * DH];   // 256 MB: encoder output (b_enc+b_h folded in)
__device__ float g_hT[DH * BATCH];                     // h transposed: [H][B]
__device__ float g_part[NKC * BATCH * DH];             // split-K partials: 4 MB
__device__ unsigned g_count;                           // barrier arrival counter (zero-init)
__device__ volatile unsigned g_gen;                    // barrier generation (monotonic)

// ---------------- f32x2 packed-FMA helpers (Blackwell FFMA2 path) ----------------
__device__ __forceinline__ unsigned long long pack2(float x) {
    unsigned long long r;
    asm("mov.b64 %0, {%1, %1};" : "=l"(r) : "f"(x));
    return r;
}
__device__ __forceinline__ void ffma2(unsigned long long& d,
                                      unsigned long long a,
                                      unsigned long long b) {
    asm("fma.rn.f32x2 %0, %1, %2, %0;" : "+l"(d) : "l"(a), "l"(b));
}
__device__ __forceinline__ float2 unpack2(unsigned long long v) {
    float2 f;
    asm("mov.b64 {%0, %1}, %2;" : "=f"(f.x), "=f"(f.y) : "l"(v));
    return f;
}

// ---------------- software grid barrier (128 resident CTAs) ----------------
__device__ __forceinline__ void grid_barrier() {
    __syncthreads();
    if (threadIdx.x == 0) {
        unsigned gen = g_gen;          // read generation BEFORE arriving
        __threadfence();               // order data writes + gen read before arrival
        unsigned a = atomicAdd(&g_count, 1u);
        if (a == gridDim.x - 1) {
            g_count = 0;
            __threadfence();           // reset visible before release
            g_gen = gen + 1;           // release
        } else {
            while (g_gen == gen) { }   // volatile spin (L2)
        }
        __threadfence();               // acquire: gpu-scope fence -> L1 invalidate
    }
    __syncthreads();
}

// =====================================================================
// Kernel 1: encoder GEMM  Wx[m][n] = X[m][:] @ W_enc[:, n] + b_enc[n] + b_h[n]
// BM=128, BN=64, BK=16, 256 threads, 8x4 outputs/thread via FFMA2 (row-paired)
// =====================================================================
__global__ __launch_bounds__(256)
void encoder_gemm(const float* __restrict__ X,
                  const float* __restrict__ W,
                  const float* __restrict__ bias,
                  const float* __restrict__ bias2) {
    __shared__ float As[16 * 128];   // As[k][m]  (transposed tile)
    __shared__ float Bs[16 * 64];    // Bs[k][n]

    const int m0  = blockIdx.y * 128;
    const int n0  = blockIdx.x * 64;
    const int tid = threadIdx.x;
    const int tc  = tid & 15;        // 16 col-groups x 4 cols
    const int tr  = tid >> 4;        // 16 row-groups x 8 rows

    unsigned long long A[4][4];
#pragma unroll
    for (int i = 0; i < 4; i++)
#pragma unroll
        for (int j = 0; j < 4; j++) A[i][j] = 0ull;

    for (int kb = 0; kb < DIN; kb += 16) {
        // Load A tile (128x16) transposed into As[k][m]
        {
            int f = tid;
#pragma unroll
            for (int it = 0; it < 2; ++it, f += 256) {
                int row = f >> 2;
                int kq  = f & 3;
                float4 v = *(const float4*)(X + (size_t)(m0 + row) * DIN + kb + kq * 4);
                As[(kq * 4 + 0) * 128 + row] = v.x;
                As[(kq * 4 + 1) * 128 + row] = v.y;
                As[(kq * 4 + 2) * 128 + row] = v.z;
                As[(kq * 4 + 3) * 128 + row] = v.w;
            }
        }
        // Load B tile (16x64)
        {
            int row = tid >> 4;
            int c4  = tid & 15;
            float4 v = *(const float4*)(W + (size_t)(kb + row) * DH + n0 + c4 * 4);
            *(float4*)(Bs + row * 64 + c4 * 4) = v;
        }
        __syncthreads();

#pragma unroll
        for (int k = 0; k < 16; k++) {
            const ulonglong2* hp = (const ulonglong2*)(As + k * 128 + tr * 8);
            ulonglong2 a01 = hp[0];
            ulonglong2 a23 = hp[1];
            unsigned long long av[4] = { a01.x, a01.y, a23.x, a23.y };
            float4 w = *(const float4*)(Bs + k * 64 + tc * 4);
            unsigned long long wv[4] = { pack2(w.x), pack2(w.y), pack2(w.z), pack2(w.w) };
#pragma unroll
            for (int rp = 0; rp < 4; rp++)
#pragma unroll
                for (int c = 0; c < 4; c++) ffma2(A[rp][c], av[rp], wv[c]);
        }
        __syncthreads();
    }

    // Epilogue: + b_enc + b_h, write Wx
    float4 be = *(const float4*)(bias  + n0 + tc * 4);
    float4 bh = *(const float4*)(bias2 + n0 + tc * 4);
    be.x += bh.x; be.y += bh.y; be.z += bh.z; be.w += bh.w;
#pragma unroll
    for (int rp = 0; rp < 4; rp++) {
        float2 c0 = unpack2(A[rp][0]);
        float2 c1 = unpack2(A[rp][1]);
        float2 c2 = unpack2(A[rp][2]);
        float2 c3 = unpack2(A[rp][3]);
        int row = tr * 8 + rp * 2;
        float4 lo = { c0.x + be.x, c1.x + be.y, c2.x + be.z, c3.x + be.w };
        float4 hi = { c0.y + be.x, c1.y + be.y, c2.y + be.z, c3.y + be.w };
        *(float4*)(g_Wx + (size_t)(m0 + row)     * DH + n0 + tc * 4) = lo;
        *(float4*)(g_Wx + (size_t)(m0 + row + 1) * DH + n0 + tc * 4) = hi;
    }
}

// =====================================================================
// Kernel 2: persistent scan. 128 CTAs x 512 threads.
// CTA (jt, kc): 64-col tile x 128-k chunk. 512 threads = 2 groups of 256,
// each group computes half the k range (64 k) of the SAME 128x64 output
// tile; halves combined via conflict-free SMEM reduce, then one g_part store.
// Phase 2: 32b x 32j tile per CTA, SMEM transpose -> coalesced g_hT writes.
// Wx[t] prefetched before barrier 1 (bias pre-folded by encoder).
// =====================================================================
__global__ __launch_bounds__(SCAN_THREADS)
void scan_kernel(const float* __restrict__ h0,
                 const float* __restrict__ Wh,
                 float* __restrict__ out) {
    extern __shared__ float smem[];
    float* Ws = smem;                 // [128][64]  W_h slice (persists all steps)
    float* hs = smem + 128 * 64;      // [128][128] h slice / reduce buf / transpose buf

    const int tid = threadIdx.x;
    const int cta = blockIdx.x;
    const int jbase = (cta & 15) * 64;
    const int kc    = cta >> 4;
    const int kbase = kc * 128;

    const int half = tid >> 8;        // 0: k in [0,64), 1: k in [64,128)
    const int tg   = tid & 255;
    const int tc   = tg & 15;         // 4 cols each
    const int tr   = tg >> 4;         // 8 rows each

    // phase-2 element mapping (32b x 32j tile per CTA, 2 elems/thread)
    const int p_b = (cta & 3) * 32 + (tid >> 4);
    const int p_j = (cta >> 2) * 32 + (tid & 15) * 2;

    // Preload W_h slice [kbase..kbase+128) x [jbase..jbase+64) into SMEM (once)
    for (int i = tid; i < 128 * 16; i += SCAN_THREADS) {
        int row = i >> 4, c4 = i & 15;
        *(float4*)(Ws + row * 64 + c4 * 4) =
            *(const float4*)(Wh + (size_t)(kbase + row) * DH + jbase + c4 * 4);
    }
    // Initialize g_hT (transposed h0) — one-time scatter, off the steady path
    for (int i = tid + cta * SCAN_THREADS; i < DH * BATCH; i += SCAN_CTAS * SCAN_THREADS) {
        int j = i >> 7;
        int b = i & 127;
        g_hT[i] = h0[(size_t)b * DH + j];
    }
    grid_barrier();

    for (int t = 0; t < T_STEPS; ++t) {
        // -------- stage h slice (contiguous 64KB copy: g_hT is k-major) --------
        {
            const float4* src = (const float4*)(g_hT + kbase * BATCH);
            float4* dst = (float4*)hs;
            for (int i = tid; i < (128 * 128) / 4; i += SCAN_THREADS) dst[i] = src[i];
        }
        __syncthreads();

        // -------- phase 1: partial C[b][j] over this group's 64-k subrange --------
        unsigned long long A[4][4];
#pragma unroll
        for (int i = 0; i < 4; i++)
#pragma unroll
            for (int j = 0; j < 4; j++) A[i][j] = 0ull;

        const int k0 = half * 64;
#pragma unroll 8
        for (int kk = 0; kk < 64; kk++) {
            const int k = k0 + kk;
            const ulonglong2* hp = (const ulonglong2*)(hs + k * 128 + tr * 8);
            ulonglong2 a01 = hp[0];
            ulonglong2 a23 = hp[1];
            unsigned long long av[4] = { a01.x, a01.y, a23.x, a23.y };
            float4 w = *(const float4*)(Ws + k * 64 + tc * 4);
            unsigned long long wv[4] = { pack2(w.x), pack2(w.y), pack2(w.z), pack2(w.w) };
#pragma unroll
            for (int rp = 0; rp < 4; rp++)
#pragma unroll
                for (int c = 0; c < 4; c++) ffma2(A[rp][c], av[rp], wv[c]);
        }

        // Unpack accumulators to 8 float4 (rp*2 + {lo,hi} rows)
        float4 mine[8];
#pragma unroll
        for (int rp = 0; rp < 4; rp++) {
            float2 c0 = unpack2(A[rp][0]);
            float2 c1 = unpack2(A[rp][1]);
            float2 c2 = unpack2(A[rp][2]);
            float2 c3 = unpack2(A[rp][3]);
            mine[rp * 2 + 0] = make_float4(c0.x, c1.x, c2.x, c3.x);
            mine[rp * 2 + 1] = make_float4(c0.y, c1.y, c2.y, c3.y);
        }

        // -------- intra-CTA k-half reduce (conflict-free: slot = i*256 + tg) ----
        __syncthreads();                      // all done reading hs
        float4* rb = (float4*)hs;             // reuse hs as reduce buffer (32KB)
        if (half == 1) {
#pragma unroll
            for (int i = 0; i < 8; i++) rb[i * 256 + tg] = mine[i];
        }
        __syncthreads();
        if (half == 0) {
#pragma unroll
            for (int i = 0; i < 8; i++) {
                float4 v = mine[i];
                float4 o = rb[i * 256 + tg];
                v.x += o.x; v.y += o.y; v.z += o.z; v.w += o.w;
                int b = tr * 8 + (i >> 1) * 2 + (i & 1);
                *(float4*)(g_part + ((size_t)(kc * 128 + b)) * DH + jbase + tc * 4) = v;
            }
        }

        // -------- prefetch Wx[t] (bias pre-folded) — overlaps barrier wait ------
        float2 s = *(const float2*)(g_Wx + (size_t)t * BATCH * DH + (size_t)p_b * DH + p_j);

        grid_barrier();                       // partials visible everywhere

        // -------- phase 2: reduce 8 partials, tanh, SMEM-transpose, store -------
#pragma unroll
        for (int kk = 0; kk < NKC; kk++) {
            float2 p = *(const float2*)(g_part + ((size_t)(kk * 128 + p_b)) * DH + p_j);
            s.x += p.x; s.y += p.y;
        }
        s.x = tanhf(s.x);
        s.y = tanhf(s.y);
        if (t == T_STEPS - 1) *(float2*)(out + (size_t)p_b * DH + p_j) = s;  // natural [B][H]

        {
            // transpose 32x32 tile through padded SMEM (conflict-free both ways)
            float* sm = hs;                   // [32][33]
            int bl  = tid >> 4;
            int jh2 = (tid & 15) * 2;
            sm[bl * 33 + jh2]     = s.x;
            sm[bl * 33 + jh2 + 1] = s.y;
            __syncthreads();
            int jl = tid >> 4;
            int bp = (tid & 15) * 2;
            float2 o2 = make_float2(sm[bp * 33 + jl], sm[(bp + 1) * 33 + jl]);
            int jg = (cta >> 2) * 32 + jl;
            int bg = (cta & 3) * 32 + bp;
            *(float2*)(g_hT + (size_t)jg * BATCH + bg) = o2;   // coalesced 128B/warp
        }

        grid_barrier();                       // h fully written before next stage
    }
}

// =====================================================================
// Launch
// =====================================================================
extern "C" void kernel_launch(void* const* d_in, const int* in_sizes, int n_in,
                              void* d_out, int out_size) {
    (void)in_sizes; (void)n_in; (void)out_size;
    const float* X     = (const float*)d_in[0];
    const float* h0    = (const float*)d_in[1];
    const float* W_enc = (const float*)d_in[2];
    const float* b_enc = (const float*)d_in[3];
    const float* W_h   = (const float*)d_in[4];
    const float* b_h   = (const float*)d_in[5];
    float* out = (float*)d_out;

    // Encoder: Wx = X @ W_enc + b_enc + b_h   (grid 16 x 512)
    dim3 egrid(DH / 64, M_TOTAL / 128);
    encoder_gemm<<<egrid, 256>>>(X, W_enc, b_enc, b_h);

    // Persistent scan (single wave: 128 CTAs, 96KB dynamic smem, 512 threads)
    const int scan_smem = (128 * 64 + 128 * 128) * (int)sizeof(float);  // 98304
    cudaFuncSetAttribute(scan_kernel, cudaFuncAttributeMaxDynamicSharedMemorySize, scan_smem);
    scan_kernel<<<SCAN_CTAS, SCAN_THREADS, scan_smem>>>(h0, W_h, out);
}

// round 15
// speedup vs baseline: 1.1401x; 1.0303x over previous
#include <cuda_runtime.h>
#include <cuda_bf16.h>
#include <mma.h>
#include <cstdint>
#include <cstddef>

using namespace nvcuda;

#define T_STEPS 512
#define BATCH   128
#define DIN     512
#define DH      1024
#define M_TOTAL (T_STEPS * BATCH)   // 65536
#define NKC     8
#define SCAN_CTAS 128
#define SCAN_THREADS 512

// ---------------- scratch (static __device__ — allocation-free) ----------------
__device__ float g_Wx[(size_t)T_STEPS * BATCH * DH];   // encoder out (b_enc+b_h folded)
__device__ float g_hT[DH * BATCH];                     // h transposed: [H][B]  (fp32, R4-proven)
__device__ float g_part[NKC * BATCH * DH];             // split-K partials [kc*128+b][j]
__device__ unsigned g_count;
__device__ volatile unsigned g_gen;

// ---------------- f32x2 packed-FMA helpers (encoder, R4-proven) ----------------
__device__ __forceinline__ unsigned long long pack2(float x) {
    unsigned long long r;
    asm("mov.b64 %0, {%1, %1};" : "=l"(r) : "f"(x));
    return r;
}
__device__ __forceinline__ void ffma2(unsigned long long& d,
                                      unsigned long long a,
                                      unsigned long long b) {
    asm("fma.rn.f32x2 %0, %1, %2, %0;" : "+l"(d) : "l"(a), "l"(b));
}
__device__ __forceinline__ float2 unpack2(unsigned long long v) {
    float2 f;
    asm("mov.b64 {%0, %1}, %2;" : "=f"(f.x), "=f"(f.y) : "l"(v));
    return f;
}

union U4H { unsigned long long u; __nv_bfloat16 h[4]; };

__device__ __forceinline__ void split_bf16(float v, __nv_bfloat16& hi, __nv_bfloat16& lo) {
    hi = __float2bfloat16(v);
    lo = __float2bfloat16(v - __bfloat162float(hi));
}

// ---------------- software grid barrier (R4-proven, verbatim) ----------------
__device__ __forceinline__ void grid_barrier() {
    __syncthreads();
    if (threadIdx.x == 0) {
        unsigned gen = g_gen;
        __threadfence();
        unsigned a = atomicAdd(&g_count, 1u);
        if (a == gridDim.x - 1) {
            g_count = 0;
            __threadfence();
            g_gen = gen + 1;
        } else {
            while (g_gen == gen) { }
        }
        __threadfence();
    }
    __syncthreads();
}

// =====================================================================
// Kernel 1: encoder GEMM (FFMA2, verbatim from passing R4 build)
// Wx[m][n] = X[m][:] @ W_enc[:, n] + b_enc[n] + b_h[n]
// =====================================================================
__global__ __launch_bounds__(256)
void encoder_gemm(const float* __restrict__ X, const float* __restrict__ W,
                  const float* __restrict__ bias, const float* __restrict__ bias2) {
    __shared__ float As[16 * 128];
    __shared__ float Bs[16 * 64];
    const int m0 = blockIdx.y * 128;
    const int n0 = blockIdx.x * 64;
    const int tid = threadIdx.x;
    const int tc = tid & 15;
    const int tr = tid >> 4;

    unsigned long long A[4][4];
#pragma unroll
    for (int i = 0; i < 4; i++)
#pragma unroll
        for (int j = 0; j < 4; j++) A[i][j] = 0ull;

    for (int kb = 0; kb < DIN; kb += 16) {
        {
            int f = tid;
#pragma unroll
            for (int it = 0; it < 2; ++it, f += 256) {
                int row = f >> 2, kq = f & 3;
                float4 v = *(const float4*)(X + (size_t)(m0 + row) * DIN + kb + kq * 4);
                As[(kq * 4 + 0) * 128 + row] = v.x;
                As[(kq * 4 + 1) * 128 + row] = v.y;
                As[(kq * 4 + 2) * 128 + row] = v.z;
                As[(kq * 4 + 3) * 128 + row] = v.w;
            }
        }
        {
            int row = tid >> 4, c4 = tid & 15;
            *(float4*)(Bs + row * 64 + c4 * 4) =
                *(const float4*)(W + (size_t)(kb + row) * DH + n0 + c4 * 4);
        }
        __syncthreads();
#pragma unroll
        for (int k = 0; k < 16; k++) {
            const ulonglong2* hp = (const ulonglong2*)(As + k * 128 + tr * 8);
            ulonglong2 a01 = hp[0], a23 = hp[1];
            unsigned long long av[4] = { a01.x, a01.y, a23.x, a23.y };
            float4 w = *(const float4*)(Bs + k * 64 + tc * 4);
            unsigned long long wv[4] = { pack2(w.x), pack2(w.y), pack2(w.z), pack2(w.w) };
#pragma unroll
            for (int rp = 0; rp < 4; rp++)
#pragma unroll
                for (int c = 0; c < 4; c++) ffma2(A[rp][c], av[rp], wv[c]);
        }
        __syncthreads();
    }
    float4 be = *(const float4*)(bias + n0 + tc * 4);
    float4 bh = *(const float4*)(bias2 + n0 + tc * 4);
    be.x += bh.x; be.y += bh.y; be.z += bh.z; be.w += bh.w;
#pragma unroll
    for (int rp = 0; rp < 4; rp++) {
        float2 c0 = unpack2(A[rp][0]), c1 = unpack2(A[rp][1]);
        float2 c2 = unpack2(A[rp][2]), c3 = unpack2(A[rp][3]);
        int row = tr * 8 + rp * 2;
        float4 lo = { c0.x + be.x, c1.x + be.y, c2.x + be.z, c3.x + be.w };
        float4 hi = { c0.y + be.x, c1.y + be.y, c2.y + be.z, c3.y + be.w };
        *(float4*)(g_Wx + (size_t)(m0 + row)     * DH + n0 + tc * 4) = lo;
        *(float4*)(g_Wx + (size_t)(m0 + row + 1) * DH + n0 + tc * 4) = hi;
    }
}

// =====================================================================
// Kernel 2: persistent scan — R4 skeleton, wmma bf16 hi/lo GEMM core.
// 128 CTAs x 512 threads (16 warps). CTA (jt, kc): C[128b x 64j] over
// k in [kc*128, kc*128+128). Warp w: wb = w&7 -> b-rows [16wb,16wb+16),
// wn = w>>3 -> j-cols [32wn, 32wn+32).
// A tile: [k][b] bf16, col_major ldm 136 (staged from fp32 g_hT, no transpose).
// B tile: [k][j] bf16, row_major ldm 72 (from W_h directly, one-time).
// Phase 2 / transpose / barriers: verbatim R4 (proven).
// SMEM: sAh 34816 | sAl 34816 | sBh 18432 | sBl 18432 = 106496 B
// =====================================================================
#define S_AH 0
#define S_AL 34816
#define S_BH 69632
#define S_BL 88064
#define S_SMEM 106496

__global__ __launch_bounds__(SCAN_THREADS)
void scan_kernel(const float* __restrict__ h0, const float* __restrict__ Wh,
                 float* __restrict__ out) {
    extern __shared__ char smem[];
    __nv_bfloat16* sAh = (__nv_bfloat16*)(smem + S_AH);
    __nv_bfloat16* sAl = (__nv_bfloat16*)(smem + S_AL);
    __nv_bfloat16* sBh = (__nv_bfloat16*)(smem + S_BH);
    __nv_bfloat16* sBl = (__nv_bfloat16*)(smem + S_BL);

    const int tid = threadIdx.x;
    const int cta = blockIdx.x;
    const int wid = tid >> 5;
    const int jt = cta & 15, jbase = jt * 64;
    const int kc = cta >> 4, kbase = kc * 128;
    const int wb = wid & 7;        // b-row group
    const int wn = wid >> 3;       // j-col half

    // ---- one-time: B tiles = split(W_h[kbase+k][jbase+j]) , [k][j] ----
#pragma unroll
    for (int i = 0; i < 16; ++i) {
        int idx = tid + i * SCAN_THREADS;          // 0..8191
        int k = idx >> 6, j = idx & 63;
        float w = Wh[(size_t)(kbase + k) * DH + jbase + j];
        __nv_bfloat16 hi, lo;
        split_bf16(w, hi, lo);
        sBh[k * 72 + j] = hi;
        sBl[k * 72 + j] = lo;
    }
    // ---- one-time: g_hT init (transposed h0) — verbatim R4 ----
    for (int i = tid + cta * SCAN_THREADS; i < DH * BATCH; i += SCAN_CTAS * SCAN_THREADS) {
        int j = i >> 7;
        int b = i & 127;
        g_hT[i] = h0[(size_t)b * DH + j];
    }
    grid_barrier();

    // phase-2 mapping (verbatim R4): 32b x 32j tile per CTA, 2 elems/thread
    const int p_b = (cta & 3) * 32 + (tid >> 4);
    const int p_j = (cta >> 2) * 32 + (tid & 15) * 2;

    for (int t = 0; t < T_STEPS; ++t) {
        // ---- stage A: fp32 g_hT[k][b] -> bf16 hi/lo SMEM [k][b] (no transpose) ----
#pragma unroll
        for (int it = 0; it < 8; ++it) {
            int idx = tid + it * SCAN_THREADS;     // 0..4095 (float4 granules)
            int k = idx >> 5, b4 = (idx & 31) * 4;
            float4 v = *(const float4*)(g_hT + (size_t)(kbase + k) * BATCH + b4);
            U4H ph, pl;
            split_bf16(v.x, ph.h[0], pl.h[0]);
            split_bf16(v.y, ph.h[1], pl.h[1]);
            split_bf16(v.z, ph.h[2], pl.h[2]);
            split_bf16(v.w, ph.h[3], pl.h[3]);
            *(unsigned long long*)(sAh + k * 136 + b4) = ph.u;
            *(unsigned long long*)(sAl + k * 136 + b4) = pl.u;
        }
        __syncthreads();

        // ---- wmma: 8 k-frags x 2 n-frags x 3 terms (AhBh + AlBh + AhBl) ----
        wmma::fragment<wmma::accumulator, 16, 16, 16, float> acc[2];
        wmma::fill_fragment(acc[0], 0.0f);
        wmma::fill_fragment(acc[1], 0.0f);

#pragma unroll
        for (int k = 0; k < 8; ++k) {
            wmma::fragment<wmma::matrix_a, 16, 16, 16, __nv_bfloat16, wmma::col_major> ah, al;
            wmma::load_matrix_sync(ah, sAh + k * 16 * 136 + wb * 16, 136);
            wmma::load_matrix_sync(al, sAl + k * 16 * 136 + wb * 16, 136);
#pragma unroll
            for (int n = 0; n < 2; ++n) {
                wmma::fragment<wmma::matrix_b, 16, 16, 16, __nv_bfloat16, wmma::row_major> bh, bl;
                wmma::load_matrix_sync(bh, sBh + k * 16 * 72 + wn * 32 + n * 16, 72);
                wmma::load_matrix_sync(bl, sBl + k * 16 * 72 + wn * 32 + n * 16, 72);
                wmma::mma_sync(acc[n], ah, bh, acc[n]);
                wmma::mma_sync(acc[n], al, bh, acc[n]);
                wmma::mma_sync(acc[n], ah, bl, acc[n]);
            }
        }

        // ---- store partials: identical g_part addresses as R4 ([kc*128+b][j]) ----
#pragma unroll
        for (int n = 0; n < 2; ++n)
            wmma::store_matrix_sync(
                g_part + (size_t)(kc * 128 + wb * 16) * DH + jbase + wn * 32 + n * 16,
                acc[n], DH, wmma::mem_row_major);

        // ---- prefetch Wx[t] (bias pre-folded) — overlaps barrier wait ----
        float2 s = *(const float2*)(g_Wx + (size_t)t * BATCH * DH + (size_t)p_b * DH + p_j);

        grid_barrier();                            // partials visible everywhere

        // ---- phase 2: reduce 8 partials, tanh, SMEM-transpose, store (verbatim R4) ----
#pragma unroll
        for (int kk = 0; kk < NKC; kk++) {
            float2 p = *(const float2*)(g_part + ((size_t)(kk * 128 + p_b)) * DH + p_j);
            s.x += p.x; s.y += p.y;
        }
        s.x = tanhf(s.x);
        s.y = tanhf(s.y);
        if (t == T_STEPS - 1) *(float2*)(out + (size_t)p_b * DH + p_j) = s;

        {
            float* sm = (float*)sAh;               // alias (mma reads done pre-barrier)
            int bl = tid >> 4;
            int jh2 = (tid & 15) * 2;
            sm[bl * 33 + jh2]     = s.x;
            sm[bl * 33 + jh2 + 1] = s.y;
            __syncthreads();
            int jl = tid >> 4;
            int bp = (tid & 15) * 2;
            float2 o2 = make_float2(sm[bp * 33 + jl], sm[(bp + 1) * 33 + jl]);
            int jg = (cta >> 2) * 32 + jl;
            int bg = (cta & 3) * 32 + bp;
            *(float2*)(g_hT + (size_t)jg * BATCH + bg) = o2;   // coalesced
        }

        grid_barrier();                            // h visible before next staging
    }
}

// =====================================================================
// Launch
// =====================================================================
extern "C" void kernel_launch(void* const* d_in, const int* in_sizes, int n_in,
                              void* d_out, int out_size) {
    (void)in_sizes; (void)n_in; (void)out_size;
    const float* X     = (const float*)d_in[0];
    const float* h0    = (const float*)d_in[1];
    const float* W_enc = (const float*)d_in[2];
    const float* b_enc = (const float*)d_in[3];
    const float* W_h   = (const float*)d_in[4];
    const float* b_h   = (const float*)d_in[5];
    float* out = (float*)d_out;

    dim3 egrid(DH / 64, M_TOTAL / 128);
    encoder_gemm<<<egrid, 256>>>(X, W_enc, b_enc, b_h);

    cudaFuncSetAttribute(scan_kernel, cudaFuncAttributeMaxDynamicSharedMemorySize, S_SMEM);
    scan_kernel<<<SCAN_CTAS, SCAN_THREADS, S_SMEM>>>(h0, W_h, out);
}

// round 16
// speedup vs baseline: 1.2083x; 1.0598x over previous
#include <cuda_runtime.h>
#include <cuda_bf16.h>
#include <mma.h>
#include <cstdint>
#include <cstddef>

using namespace nvcuda;

#define T_STEPS 512
#define BATCH   128
#define DIN     512
#define DH      1024
#define M_TOTAL (T_STEPS * BATCH)   // 65536
#define NKC     8
#define SCAN_CTAS 128
#define SCAN_THREADS 512

// ---------------- scratch (static __device__ — allocation-free) ----------------
__device__ float g_Wx[(size_t)T_STEPS * BATCH * DH];   // encoder out (b_enc+b_h folded)
__device__ float g_hT[DH * BATCH];                     // h transposed: [H][B]  (fp32, proven)
__device__ float g_part[NKC * BATCH * DH];             // split-K partials [kc*128+b][j]
__device__ unsigned g_count;
__device__ volatile unsigned g_gen;

union U4H { unsigned long long u; __nv_bfloat16 h[4]; };

__device__ __forceinline__ void split_bf16(float v, __nv_bfloat16& hi, __nv_bfloat16& lo) {
    hi = __float2bfloat16(v);
    lo = __float2bfloat16(v - __bfloat162float(hi));
}

// ---------------- software grid barrier (proven, verbatim) ----------------
__device__ __forceinline__ void grid_barrier() {
    __syncthreads();
    if (threadIdx.x == 0) {
        unsigned gen = g_gen;
        __threadfence();
        unsigned a = atomicAdd(&g_count, 1u);
        if (a == gridDim.x - 1) {
            g_count = 0;
            __threadfence();
            g_gen = gen + 1;
        } else {
            while (g_gen == gen) { }
        }
        __threadfence();
    }
    __syncthreads();
}

// =====================================================================
// Kernel 1: encoder GEMM via WMMA bf16 hi/lo 3-term split.
// Wx[m][j] = X[m][:] @ W_enc[:, j] + b_enc[j] + b_h[j]
// Grid (16 n-tiles, 512 m-tiles), 256 threads (8 warps).
// BM=128, BN=64, BK=64. In-kernel fp32->bf16 split staging (R15-proven
// pattern): A staged [m][k] (native X layout) -> row_major frags;
// B staged [k][j] (native W_enc layout) -> row_major frags (proven in scan).
// =====================================================================
#define E_AH 0            // 128*72*2 = 18432
#define E_AL 18432
#define E_BH 36864        // 64*72*2 = 9216
#define E_BL 46080
#define E_BIAS 55296      // 64 floats
#define E_SMEM 55552

__global__ __launch_bounds__(256)
void encoder_wmma(const float* __restrict__ X, const float* __restrict__ W,
                  const float* __restrict__ bias, const float* __restrict__ bias2) {
    extern __shared__ char smem[];
    __nv_bfloat16* sAh = (__nv_bfloat16*)(smem + E_AH);
    __nv_bfloat16* sAl = (__nv_bfloat16*)(smem + E_AL);
    __nv_bfloat16* sBh = (__nv_bfloat16*)(smem + E_BH);
    __nv_bfloat16* sBl = (__nv_bfloat16*)(smem + E_BL);
    float* bsum = (float*)(smem + E_BIAS);

    const int n0 = blockIdx.x * 64;
    const int m0 = blockIdx.y * 128;
    const int tid = threadIdx.x;
    const int wid = tid >> 5, lane = tid & 31;
    const int wm = wid * 16;

    if (tid < 64) bsum[tid] = bias[n0 + tid] + bias2[n0 + tid];

    wmma::fragment<wmma::accumulator, 16, 16, 16, float> acc[4];
#pragma unroll
    for (int n = 0; n < 4; ++n) wmma::fill_fragment(acc[n], 0.0f);

    for (int kb = 0; kb < 8; ++kb) {
        const int k0 = kb * 64;
        // stage A: X[m0+row][k0..k0+64) fp32 -> bf16 hi/lo, [m][k] stride 72
#pragma unroll
        for (int it = 0; it < 8; ++it) {
            int idx = tid + it * 256;              // 0..2047 float4 granules
            int row = idx >> 4, k4 = (idx & 15) * 4;
            float4 v = *(const float4*)(X + (size_t)(m0 + row) * DIN + k0 + k4);
            U4H ph, pl;
            split_bf16(v.x, ph.h[0], pl.h[0]);
            split_bf16(v.y, ph.h[1], pl.h[1]);
            split_bf16(v.z, ph.h[2], pl.h[2]);
            split_bf16(v.w, ph.h[3], pl.h[3]);
            *(unsigned long long*)(sAh + row * 72 + k4) = ph.u;
            *(unsigned long long*)(sAl + row * 72 + k4) = pl.u;
        }
        // stage B: W_enc[k0+row][n0..n0+64) fp32 -> bf16 hi/lo, [k][j] stride 72
#pragma unroll
        for (int it = 0; it < 4; ++it) {
            int idx = tid + it * 256;              // 0..1023 float4 granules
            int row = idx >> 4, j4 = (idx & 15) * 4;
            float4 v = *(const float4*)(W + (size_t)(k0 + row) * DH + n0 + j4);
            U4H ph, pl;
            split_bf16(v.x, ph.h[0], pl.h[0]);
            split_bf16(v.y, ph.h[1], pl.h[1]);
            split_bf16(v.z, ph.h[2], pl.h[2]);
            split_bf16(v.w, ph.h[3], pl.h[3]);
            *(unsigned long long*)(sBh + row * 72 + j4) = ph.u;
            *(unsigned long long*)(sBl + row * 72 + j4) = pl.u;
        }
        __syncthreads();

#pragma unroll
        for (int k = 0; k < 4; ++k) {
            wmma::fragment<wmma::matrix_a, 16, 16, 16, __nv_bfloat16, wmma::row_major> ah, al;
            wmma::load_matrix_sync(ah, sAh + wm * 72 + k * 16, 72);
            wmma::load_matrix_sync(al, sAl + wm * 72 + k * 16, 72);
#pragma unroll
            for (int n = 0; n < 4; ++n) {
                wmma::fragment<wmma::matrix_b, 16, 16, 16, __nv_bfloat16, wmma::row_major> bh, bl;
                wmma::load_matrix_sync(bh, sBh + k * 16 * 72 + n * 16, 72);
                wmma::load_matrix_sync(bl, sBl + k * 16 * 72 + n * 16, 72);
                wmma::mma_sync(acc[n], ah, bh, acc[n]);
                wmma::mma_sync(acc[n], al, bh, acc[n]);
                wmma::mma_sync(acc[n], ah, bl, acc[n]);
            }
        }
        __syncthreads();
    }

    // epilogue: per-warp scratch (reuse A region), + bias, write g_Wx
    float* scratch = (float*)smem + wid * (16 * 68);
#pragma unroll
    for (int n = 0; n < 4; ++n)
        wmma::store_matrix_sync(scratch + n * 16, acc[n], 68, wmma::mem_row_major);
    __syncwarp();
    {
        int r = lane >> 1;                  // 0..15
        int ch = (lane & 1) * 32;           // col half
        size_t rowoff = (size_t)(m0 + wm + r) * DH + n0 + ch;
#pragma unroll
        for (int c = 0; c < 32; c += 4) {
            float4 v = *(float4*)(scratch + r * 68 + ch + c);
            v.x += bsum[ch + c + 0];
            v.y += bsum[ch + c + 1];
            v.z += bsum[ch + c + 2];
            v.w += bsum[ch + c + 3];
            *(float4*)(g_Wx + rowoff + c) = v;
        }
    }
}

// =====================================================================
// Kernel 2: persistent scan — VERBATIM R15 (passing, rel_err 3.3e-6).
// =====================================================================
#define S_AH 0
#define S_AL 34816
#define S_BH 69632
#define S_BL 88064
#define S_SMEM 106496

__global__ __launch_bounds__(SCAN_THREADS)
void scan_kernel(const float* __restrict__ h0, const float* __restrict__ Wh,
                 float* __restrict__ out) {
    extern __shared__ char smem[];
    __nv_bfloat16* sAh = (__nv_bfloat16*)(smem + S_AH);
    __nv_bfloat16* sAl = (__nv_bfloat16*)(smem + S_AL);
    __nv_bfloat16* sBh = (__nv_bfloat16*)(smem + S_BH);
    __nv_bfloat16* sBl = (__nv_bfloat16*)(smem + S_BL);

    const int tid = threadIdx.x;
    const int cta = blockIdx.x;
    const int wid = tid >> 5;
    const int jt = cta & 15, jbase = jt * 64;
    const int kc = cta >> 4, kbase = kc * 128;
    const int wb = wid & 7;        // b-row group
    const int wn = wid >> 3;       // j-col half

    // ---- one-time: B tiles = split(W_h[kbase+k][jbase+j]) , [k][j] ----
#pragma unroll
    for (int i = 0; i < 16; ++i) {
        int idx = tid + i * SCAN_THREADS;          // 0..8191
        int k = idx >> 6, j = idx & 63;
        float w = Wh[(size_t)(kbase + k) * DH + jbase + j];
        __nv_bfloat16 hi, lo;
        split_bf16(w, hi, lo);
        sBh[k * 72 + j] = hi;
        sBl[k * 72 + j] = lo;
    }
    // ---- one-time: g_hT init (transposed h0) ----
    for (int i = tid + cta * SCAN_THREADS; i < DH * BATCH; i += SCAN_CTAS * SCAN_THREADS) {
        int j = i >> 7;
        int b = i & 127;
        g_hT[i] = h0[(size_t)b * DH + j];
    }
    grid_barrier();

    // phase-2 mapping: 32b x 32j tile per CTA, 2 elems/thread
    const int p_b = (cta & 3) * 32 + (tid >> 4);
    const int p_j = (cta >> 2) * 32 + (tid & 15) * 2;

    for (int t = 0; t < T_STEPS; ++t) {
        // ---- stage A: fp32 g_hT[k][b] -> bf16 hi/lo SMEM [k][b] ----
#pragma unroll
        for (int it = 0; it < 8; ++it) {
            int idx = tid + it * SCAN_THREADS;     // 0..4095 (float4 granules)
            int k = idx >> 5, b4 = (idx & 31) * 4;
            float4 v = *(const float4*)(g_hT + (size_t)(kbase + k) * BATCH + b4);
            U4H ph, pl;
            split_bf16(v.x, ph.h[0], pl.h[0]);
            split_bf16(v.y, ph.h[1], pl.h[1]);
            split_bf16(v.z, ph.h[2], pl.h[2]);
            split_bf16(v.w, ph.h[3], pl.h[3]);
            *(unsigned long long*)(sAh + k * 136 + b4) = ph.u;
            *(unsigned long long*)(sAl + k * 136 + b4) = pl.u;
        }
        __syncthreads();

        // ---- wmma: 8 k-frags x 2 n-frags x 3 terms ----
        wmma::fragment<wmma::accumulator, 16, 16, 16, float> acc[2];
        wmma::fill_fragment(acc[0], 0.0f);
        wmma::fill_fragment(acc[1], 0.0f);

#pragma unroll
        for (int k = 0; k < 8; ++k) {
            wmma::fragment<wmma::matrix_a, 16, 16, 16, __nv_bfloat16, wmma::col_major> ah, al;
            wmma::load_matrix_sync(ah, sAh + k * 16 * 136 + wb * 16, 136);
            wmma::load_matrix_sync(al, sAl + k * 16 * 136 + wb * 16, 136);
#pragma unroll
            for (int n = 0; n < 2; ++n) {
                wmma::fragment<wmma::matrix_b, 16, 16, 16, __nv_bfloat16, wmma::row_major> bh, bl;
                wmma::load_matrix_sync(bh, sBh + k * 16 * 72 + wn * 32 + n * 16, 72);
                wmma::load_matrix_sync(bl, sBl + k * 16 * 72 + wn * 32 + n * 16, 72);
                wmma::mma_sync(acc[n], ah, bh, acc[n]);
                wmma::mma_sync(acc[n], al, bh, acc[n]);
                wmma::mma_sync(acc[n], ah, bl, acc[n]);
            }
        }

        // ---- store partials: g_part[kc*128+b][j] ----
#pragma unroll
        for (int n = 0; n < 2; ++n)
            wmma::store_matrix_sync(
                g_part + (size_t)(kc * 128 + wb * 16) * DH + jbase + wn * 32 + n * 16,
                acc[n], DH, wmma::mem_row_major);

        // ---- prefetch Wx[t] (bias pre-folded) — overlaps barrier wait ----
        float2 s = *(const float2*)(g_Wx + (size_t)t * BATCH * DH + (size_t)p_b * DH + p_j);

        grid_barrier();                            // partials visible everywhere

        // ---- phase 2: reduce 8 partials, tanh, SMEM-transpose, store ----
#pragma unroll
        for (int kk = 0; kk < NKC; kk++) {
            float2 p = *(const float2*)(g_part + ((size_t)(kk * 128 + p_b)) * DH + p_j);
            s.x += p.x; s.y += p.y;
        }
        s.x = tanhf(s.x);
        s.y = tanhf(s.y);
        if (t == T_STEPS - 1) *(float2*)(out + (size_t)p_b * DH + p_j) = s;

        {
            float* sm = (float*)sAh;               // alias (mma reads done pre-barrier)
            int bl = tid >> 4;
            int jh2 = (tid & 15) * 2;
            sm[bl * 33 + jh2]     = s.x;
            sm[bl * 33 + jh2 + 1] = s.y;
            __syncthreads();
            int jl = tid >> 4;
            int bp = (tid & 15) * 2;
            float2 o2 = make_float2(sm[bp * 33 + jl], sm[(bp + 1) * 33 + jl]);
            int jg = (cta >> 2) * 32 + jl;
            int bg = (cta & 3) * 32 + bp;
            *(float2*)(g_hT + (size_t)jg * BATCH + bg) = o2;   // coalesced
        }

        grid_barrier();                            // h visible before next staging
    }
}

// =====================================================================
// Launch
// =====================================================================
extern "C" void kernel_launch(void* const* d_in, const int* in_sizes, int n_in,
                              void* d_out, int out_size) {
    (void)in_sizes; (void)n_in; (void)out_size;
    const float* X     = (const float*)d_in[0];
    const float* h0    = (const float*)d_in[1];
    const float* W_enc = (const float*)d_in[2];
    const float* b_enc = (const float*)d_in[3];
    const float* W_h   = (const float*)d_in[4];
    const float* b_h   = (const float*)d_in[5];
    float* out = (float*)d_out;

    cudaFuncSetAttribute(encoder_wmma, cudaFuncAttributeMaxDynamicSharedMemorySize, E_SMEM);
    dim3 egrid(DH / 64, M_TOTAL / 128);
    encoder_wmma<<<egrid, 256, E_SMEM>>>(X, W_enc, b_enc, b_h);

    cudaFuncSetAttribute(scan_kernel, cudaFuncAttributeMaxDynamicSharedMemorySize, S_SMEM);
    scan_kernel<<<SCAN_CTAS, SCAN_THREADS, S_SMEM>>>(h0, W_h, out);
}

// round 17
// speedup vs baseline: 1.2851x; 1.0635x over previous
#include <cuda_runtime.h>
#include <cuda_bf16.h>
#include <mma.h>
#include <cstdint>
#include <cstddef>

using namespace nvcuda;

#define T_STEPS 512
#define BATCH   128
#define DIN     512
#define DH      1024
#define M_TOTAL (T_STEPS * BATCH)   // 65536
#define NKC     8
#define SCAN_CTAS 128
#define SCAN_THREADS 512

// ---------------- scratch (static __device__ — allocation-free) ----------------
__device__ float g_Wx[(size_t)T_STEPS * BATCH * DH];   // encoder out (b_enc+b_h folded)
__device__ __nv_bfloat16 g_hhi[DH * BATCH];            // h hi, [k][b] (transposed)
__device__ __nv_bfloat16 g_hlo[DH * BATCH];            // h lo, [k][b]
__device__ float g_part[NKC * BATCH * DH];             // split-K partials [kc*128+b][j]
__device__ unsigned g_count;
__device__ volatile unsigned g_gen;

union U4H { unsigned long long u; __nv_bfloat16 h[4]; };

__device__ __forceinline__ void split_bf16(float v, __nv_bfloat16& hi, __nv_bfloat16& lo) {
    hi = __float2bfloat16(v);
    lo = __float2bfloat16(v - __bfloat162float(hi));
}

// ---------------- software grid barrier (proven, verbatim) ----------------
__device__ __forceinline__ void grid_barrier() {
    __syncthreads();
    if (threadIdx.x == 0) {
        unsigned gen = g_gen;
        __threadfence();
        unsigned a = atomicAdd(&g_count, 1u);
        if (a == gridDim.x - 1) {
            g_count = 0;
            __threadfence();
            g_gen = gen + 1;
        } else {
            while (g_gen == gen) { }
        }
        __threadfence();
    }
    __syncthreads();
}

// =====================================================================
// Kernel 1: encoder GEMM via WMMA bf16 hi/lo 3-term split.
// BM=128, BN=128, BK=64, 512 threads (16 warps), grid (8, 512).
// Warp w: (w&7) -> m-group of 16 rows, (w>>3) -> n-half of 64 cols.
// A staged [m][k] stride 72; B staged [k][j] stride 136. In-kernel split.
// =====================================================================
#define E_AH 0            // 128*72*2  = 18432
#define E_AL 18432
#define E_BH 36864        // 64*136*2 = 17408
#define E_BL 54272
#define E_BIAS 71680      // 128 floats
#define E_SMEM 72192

__global__ __launch_bounds__(512)
void encoder_wmma(const float* __restrict__ X, const float* __restrict__ W,
                  const float* __restrict__ bias, const float* __restrict__ bias2) {
    extern __shared__ char smem[];
    __nv_bfloat16* sAh = (__nv_bfloat16*)(smem + E_AH);
    __nv_bfloat16* sAl = (__nv_bfloat16*)(smem + E_AL);
    __nv_bfloat16* sBh = (__nv_bfloat16*)(smem + E_BH);
    __nv_bfloat16* sBl = (__nv_bfloat16*)(smem + E_BL);
    float* bsum = (float*)(smem + E_BIAS);

    const int n0 = blockIdx.x * 128;
    const int m0 = blockIdx.y * 128;
    const int tid = threadIdx.x;
    const int wid = tid >> 5, lane = tid & 31;
    const int wm = (wid & 7) * 16;     // m-group
    const int wn = (wid >> 3) * 64;    // n-half

    if (tid < 128) bsum[tid] = bias[n0 + tid] + bias2[n0 + tid];

    wmma::fragment<wmma::accumulator, 16, 16, 16, float> acc[4];
#pragma unroll
    for (int n = 0; n < 4; ++n) wmma::fill_fragment(acc[n], 0.0f);

    for (int kb = 0; kb < 8; ++kb) {
        const int k0 = kb * 64;
        // stage A: X[m0+row][k0..k0+64) -> bf16 hi/lo, [m][k] stride 72
#pragma unroll
        for (int it = 0; it < 4; ++it) {
            int idx = tid + it * 512;              // 0..2047 float4 granules
            int row = idx >> 4, k4 = (idx & 15) * 4;
            float4 v = *(const float4*)(X + (size_t)(m0 + row) * DIN + k0 + k4);
            U4H ph, pl;
            split_bf16(v.x, ph.h[0], pl.h[0]);
            split_bf16(v.y, ph.h[1], pl.h[1]);
            split_bf16(v.z, ph.h[2], pl.h[2]);
            split_bf16(v.w, ph.h[3], pl.h[3]);
            *(unsigned long long*)(sAh + row * 72 + k4) = ph.u;
            *(unsigned long long*)(sAl + row * 72 + k4) = pl.u;
        }
        // stage B: W_enc[k0+row][n0..n0+128) -> bf16 hi/lo, [k][j] stride 136
#pragma unroll
        for (int it = 0; it < 4; ++it) {
            int idx = tid + it * 512;              // 0..2047 float4 granules
            int row = idx >> 5, j4 = (idx & 31) * 4;
            float4 v = *(const float4*)(W + (size_t)(k0 + row) * DH + n0 + j4);
            U4H ph, pl;
            split_bf16(v.x, ph.h[0], pl.h[0]);
            split_bf16(v.y, ph.h[1], pl.h[1]);
            split_bf16(v.z, ph.h[2], pl.h[2]);
            split_bf16(v.w, ph.h[3], pl.h[3]);
            *(unsigned long long*)(sBh + row * 136 + j4) = ph.u;
            *(unsigned long long*)(sBl + row * 136 + j4) = pl.u;
        }
        __syncthreads();

#pragma unroll
        for (int k = 0; k < 4; ++k) {
            wmma::fragment<wmma::matrix_a, 16, 16, 16, __nv_bfloat16, wmma::row_major> ah, al;
            wmma::load_matrix_sync(ah, sAh + wm * 72 + k * 16, 72);
            wmma::load_matrix_sync(al, sAl + wm * 72 + k * 16, 72);
#pragma unroll
            for (int n = 0; n < 4; ++n) {
                wmma::fragment<wmma::matrix_b, 16, 16, 16, __nv_bfloat16, wmma::row_major> bh, bl;
                wmma::load_matrix_sync(bh, sBh + k * 16 * 136 + wn + n * 16, 136);
                wmma::load_matrix_sync(bl, sBl + k * 16 * 136 + wn + n * 16, 136);
                wmma::mma_sync(acc[n], ah, bh, acc[n]);
                wmma::mma_sync(acc[n], al, bh, acc[n]);
                wmma::mma_sync(acc[n], ah, bl, acc[n]);
            }
        }
        __syncthreads();
    }

    // epilogue: per-warp scratch (16*68 floats each), + bias, write g_Wx
    float* scratch = (float*)smem + wid * (16 * 68);   // 16*4352B = 69632 <= 71680
#pragma unroll
    for (int n = 0; n < 4; ++n)
        wmma::store_matrix_sync(scratch + n * 16, acc[n], 68, wmma::mem_row_major);
    __syncwarp();
    {
        int r = lane >> 1;                  // 0..15
        int ch = (lane & 1) * 32;           // col half of this warp's 64
        size_t rowoff = (size_t)(m0 + wm + r) * DH + n0 + wn + ch;
#pragma unroll
        for (int c = 0; c < 32; c += 4) {
            float4 v = *(float4*)(scratch + r * 68 + ch + c);
            v.x += bsum[wn + ch + c + 0];
            v.y += bsum[wn + ch + c + 1];
            v.z += bsum[wn + ch + c + 2];
            v.w += bsum[wn + ch + c + 3];
            *(float4*)(g_Wx + rowoff + c) = v;
        }
    }
}

// =====================================================================
// Kernel 2: persistent scan — R15/R16 skeleton; h state now bf16 hi/lo
// in global [k][b], split once at write time; staging = pure copies.
// =====================================================================
#define S_AH 0
#define S_AL 34816
#define S_BH 69632
#define S_BL 88064
#define S_SMEM 106496

__global__ __launch_bounds__(SCAN_THREADS)
void scan_kernel(const float* __restrict__ h0, const float* __restrict__ Wh,
                 float* __restrict__ out) {
    extern __shared__ char smem[];
    __nv_bfloat16* sAh = (__nv_bfloat16*)(smem + S_AH);
    __nv_bfloat16* sAl = (__nv_bfloat16*)(smem + S_AL);
    __nv_bfloat16* sBh = (__nv_bfloat16*)(smem + S_BH);
    __nv_bfloat16* sBl = (__nv_bfloat16*)(smem + S_BL);

    const int tid = threadIdx.x;
    const int cta = blockIdx.x;
    const int wid = tid >> 5;
    const int jt = cta & 15, jbase = jt * 64;
    const int kc = cta >> 4, kbase = kc * 128;
    const int wb = wid & 7;        // b-row group
    const int wn = wid >> 3;       // j-col half

    // ---- one-time: B tiles = split(W_h[kbase+k][jbase+j]) , [k][j] ----
#pragma unroll
    for (int i = 0; i < 16; ++i) {
        int idx = tid + i * SCAN_THREADS;          // 0..8191
        int k = idx >> 6, j = idx & 63;
        float w = Wh[(size_t)(kbase + k) * DH + jbase + j];
        __nv_bfloat16 hi, lo;
        split_bf16(w, hi, lo);
        sBh[k * 72 + j] = hi;
        sBl[k * 72 + j] = lo;
    }
    // ---- one-time: h0 -> g_hhi/g_hlo (transposed [k][b], split once) ----
    for (int i = tid + cta * SCAN_THREADS; i < DH * BATCH; i += SCAN_CTAS * SCAN_THREADS) {
        int j = i >> 7;
        int b = i & 127;
        __nv_bfloat16 hi, lo;
        split_bf16(h0[(size_t)b * DH + j], hi, lo);
        g_hhi[i] = hi;
        g_hlo[i] = lo;
    }
    grid_barrier();

    // phase-2 mapping: 32b x 32j tile per CTA, 2 elems/thread
    const int p_b = (cta & 3) * 32 + (tid >> 4);
    const int p_j = (cta >> 2) * 32 + (tid & 15) * 2;

    for (int t = 0; t < T_STEPS; ++t) {
        // ---- stage A: pure uint4 copies of bf16 hi/lo [k][b] slices ----
#pragma unroll
        for (int it = 0; it < 4; ++it) {
            int idx = tid + it * SCAN_THREADS;     // 0..2047 (8-bf16 granules)
            int k = idx >> 4, b8 = (idx & 15) * 8;
            size_t g = (size_t)(kbase + k) * BATCH + b8;
            *(uint4*)(sAh + k * 136 + b8) = *(const uint4*)(g_hhi + g);
            *(uint4*)(sAl + k * 136 + b8) = *(const uint4*)(g_hlo + g);
        }
        __syncthreads();

        // ---- wmma: 8 k-frags x 2 n-frags x 3 terms ----
        wmma::fragment<wmma::accumulator, 16, 16, 16, float> acc[2];
        wmma::fill_fragment(acc[0], 0.0f);
        wmma::fill_fragment(acc[1], 0.0f);

#pragma unroll
        for (int k = 0; k < 8; ++k) {
            wmma::fragment<wmma::matrix_a, 16, 16, 16, __nv_bfloat16, wmma::col_major> ah, al;
            wmma::load_matrix_sync(ah, sAh + k * 16 * 136 + wb * 16, 136);
            wmma::load_matrix_sync(al, sAl + k * 16 * 136 + wb * 16, 136);
#pragma unroll
            for (int n = 0; n < 2; ++n) {
                wmma::fragment<wmma::matrix_b, 16, 16, 16, __nv_bfloat16, wmma::row_major> bh, bl;
                wmma::load_matrix_sync(bh, sBh + k * 16 * 72 + wn * 32 + n * 16, 72);
                wmma::load_matrix_sync(bl, sBl + k * 16 * 72 + wn * 32 + n * 16, 72);
                wmma::mma_sync(acc[n], ah, bh, acc[n]);
                wmma::mma_sync(acc[n], al, bh, acc[n]);
                wmma::mma_sync(acc[n], ah, bl, acc[n]);
            }
        }

        // ---- store partials: g_part[kc*128+b][j] ----
#pragma unroll
        for (int n = 0; n < 2; ++n)
            wmma::store_matrix_sync(
                g_part + (size_t)(kc * 128 + wb * 16) * DH + jbase + wn * 32 + n * 16,
                acc[n], DH, wmma::mem_row_major);

        // ---- prefetch Wx[t] (bias pre-folded) — overlaps barrier wait ----
        float2 s = *(const float2*)(g_Wx + (size_t)t * BATCH * DH + (size_t)p_b * DH + p_j);

        grid_barrier();                            // partials visible everywhere

        // ---- phase 2: reduce 8 partials, tanh, SMEM-transpose, store ----
#pragma unroll
        for (int kk = 0; kk < NKC; kk++) {
            float2 p = *(const float2*)(g_part + ((size_t)(kk * 128 + p_b)) * DH + p_j);
            s.x += p.x; s.y += p.y;
        }
        s.x = tanhf(s.x);
        s.y = tanhf(s.y);
        if (t == T_STEPS - 1) *(float2*)(out + (size_t)p_b * DH + p_j) = s;

        {
            float* sm = (float*)sAh;               // alias (mma reads done pre-barrier)
            int bl = tid >> 4;
            int jh2 = (tid & 15) * 2;
            sm[bl * 33 + jh2]     = s.x;
            sm[bl * 33 + jh2 + 1] = s.y;
            __syncthreads();
            int jl = tid >> 4;
            int bp = (tid & 15) * 2;
            float2 o2 = make_float2(sm[bp * 33 + jl], sm[(bp + 1) * 33 + jl]);
            int jg = (cta >> 2) * 32 + jl;
            int bg = (cta & 3) * 32 + bp;
            // split once at write: h hi/lo bf16 pairs (2 consecutive b)
            __nv_bfloat16 h0b, l0b, h1b, l1b;
            split_bf16(o2.x, h0b, l0b);
            split_bf16(o2.y, h1b, l1b);
            __nv_bfloat162 hp; hp.x = h0b; hp.y = h1b;
            __nv_bfloat162 lp; lp.x = l0b; lp.y = l1b;
            *(__nv_bfloat162*)(g_hhi + (size_t)jg * BATCH + bg) = hp;
            *(__nv_bfloat162*)(g_hlo + (size_t)jg * BATCH + bg) = lp;
        }

        grid_barrier();                            // h visible before next staging
    }
}

// =====================================================================
// Launch
// =====================================================================
extern "C" void kernel_launch(void* const* d_in, const int* in_sizes, int n_in,
                              void* d_out, int out_size) {
    (void)in_sizes; (void)n_in; (void)out_size;
    const float* X     = (const float*)d_in[0];
    const float* h0    = (const float*)d_in[1];
    const float* W_enc = (const float*)d_in[2];
    const float* b_enc = (const float*)d_in[3];
    const float* W_h   = (const float*)d_in[4];
    const float* b_h   = (const float*)d_in[5];
    float* out = (float*)d_out;

    cudaFuncSetAttribute(encoder_wmma, cudaFuncAttributeMaxDynamicSharedMemorySize, E_SMEM);
    dim3 egrid(DH / 128, M_TOTAL / 128);
    encoder_wmma<<<egrid, 512, E_SMEM>>>(X, W_enc, b_enc, b_h);

    cudaFuncSetAttribute(scan_kernel, cudaFuncAttributeMaxDynamicSharedMemorySize, S_SMEM);
    scan_kernel<<<SCAN_CTAS, SCAN_THREADS, S_SMEM>>>(h0, W_h, out);
}